// round 1
// baseline (speedup 1.0000x reference)
#include <cuda_runtime.h>
#include <math.h>
#include <stdint.h>

#define HH 128
#define WW 128
#define CFEAT 1024
#define CMID 512
#define NA 9
#define NPIX (HH*WW)
#define NIT (NPIX*NA)          // 147456
#define MAXOUT 300
#define SBLK (NIT/1024)        // 144
#define IMG_MAX 2048.0f

// ---------------- scratch (device globals; no allocation allowed) -------------
__device__ float g_x1[NPIX*CMID];        // conv1 output (relu'd)
__device__ float g_x2[NPIX*CMID];        // conv2 output (no relu)
__device__ float g_boxes[NIT*4];         // decoded clipped boxes y1,x1,y2,x2
__device__ float g_scores[NIT];          // sigmoid scores
__device__ unsigned g_key[2][NIT];
__device__ unsigned g_val[2][NIT];
__device__ unsigned g_counts[256*SBLK];
__device__ unsigned g_offs[256*SBLK];

// ---------------- 3x3 conv as tiled implicit GEMM ----------------------------
// block: 128 pixels (one image row) x 128 out-channels. 256 threads, 8x8 micro.
template<int CIN, bool RELU_IN, bool RELU_OUT>
__global__ __launch_bounds__(256, 2)
void conv3x3_kernel(const float* __restrict__ in,   // [H][W][CIN]
                    const float* __restrict__ w,    // [3][3][CIN][COUT]
                    const float* __restrict__ bias, // [COUT]
                    float* __restrict__ out,        // [H][W][COUT]
                    int COUT)
{
    const int n0  = blockIdx.x * 128;
    const int y   = blockIdx.y;
    const int tid = threadIdx.x;
    const int tx  = tid & 15;       // n dir
    const int ty  = tid >> 4;       // m dir

    __shared__ float As[16][132];
    __shared__ float Bs[16][128];

    float acc[8][8];
#pragma unroll
    for (int i = 0; i < 8; ++i)
#pragma unroll
        for (int j = 0; j < 8; ++j) acc[i][j] = 0.f;

#pragma unroll 1
    for (int tap = 0; tap < 9; ++tap) {
        const int ky = tap / 3, kx = tap % 3;
        const int yy = y + ky - 1;
        const bool rowok = ((unsigned)yy < (unsigned)HH);
        const float* inrow = in + (size_t)yy * WW * CIN;
        const float* wtap  = w  + (size_t)tap * CIN * COUT;

#pragma unroll 1
        for (int c0 = 0; c0 < CIN; c0 += 16) {
            // load A tile (transposed into [k][m])
#pragma unroll
            for (int u = 0; u < 2; ++u) {
                int id = tid + u * 256;
                int m  = id >> 2;
                int k4 = (id & 3) * 4;
                int xx = m + kx - 1;
                float4 v = make_float4(0.f, 0.f, 0.f, 0.f);
                if (rowok && (unsigned)xx < (unsigned)WW) {
                    v = *(const float4*)(inrow + (size_t)xx * CIN + c0 + k4);
                    if (RELU_IN) {
                        v.x = fmaxf(v.x, 0.f); v.y = fmaxf(v.y, 0.f);
                        v.z = fmaxf(v.z, 0.f); v.w = fmaxf(v.w, 0.f);
                    }
                }
                As[k4 + 0][m] = v.x; As[k4 + 1][m] = v.y;
                As[k4 + 2][m] = v.z; As[k4 + 3][m] = v.w;
            }
            // load B tile
#pragma unroll
            for (int u = 0; u < 2; ++u) {
                int id = tid + u * 256;
                int kb = id >> 5;
                int nb = (id & 31) * 4;
                float4 v = *(const float4*)(wtap + (size_t)(c0 + kb) * COUT + n0 + nb);
                *(float4*)&Bs[kb][nb] = v;
            }
            __syncthreads();
#pragma unroll
            for (int k = 0; k < 16; ++k) {
                float a[8], b[8];
#pragma unroll
                for (int i = 0; i < 8; ++i) a[i] = As[k][ty * 8 + i];
#pragma unroll
                for (int j = 0; j < 8; ++j) b[j] = Bs[k][tx * 8 + j];
#pragma unroll
                for (int i = 0; i < 8; ++i)
#pragma unroll
                    for (int j = 0; j < 8; ++j) acc[i][j] = fmaf(a[i], b[j], acc[i][j]);
            }
            __syncthreads();
        }
    }

    float bv[8];
#pragma unroll
    for (int j = 0; j < 8; ++j) bv[j] = bias[n0 + tx * 8 + j];

#pragma unroll
    for (int i = 0; i < 8; ++i) {
        int m = ty * 8 + i;
        float* orow = out + ((size_t)(y * WW + m)) * COUT + n0 + tx * 8;
        float v[8];
#pragma unroll
        for (int j = 0; j < 8; ++j) {
            v[j] = acc[i][j] + bv[j];
            if (RELU_OUT) v[j] = fmaxf(v[j], 0.f);
        }
        *(float4*)(orow + 0) = make_float4(v[0], v[1], v[2], v[3]);
        *(float4*)(orow + 4) = make_float4(v[4], v[5], v[6], v[7]);
    }
}

// ---------------- head: 1x1 convs + sigmoid + decode --------------------------
__global__ __launch_bounds__(256)
void head_kernel(const float* __restrict__ x2,
                 const float* __restrict__ wsc, const float* __restrict__ bsc,
                 const float* __restrict__ wbx, const float* __restrict__ bbx)
{
    const int p0  = blockIdx.x * 64;     // pixel base
    const int tid = threadIdx.x;
    const int px  = tid & 63;
    const int g   = tid >> 6;            // 0..3

    __shared__ float xs[64][65];
    __shared__ float wsm[64][46];
    __shared__ float zb[64][48];

    float acc[12];
#pragma unroll
    for (int j = 0; j < 12; ++j) acc[j] = 0.f;

#pragma unroll 1
    for (int c0 = 0; c0 < CMID; c0 += 64) {
        // x2 tile: 64 px x 64 k
#pragma unroll
        for (int u = 0; u < 4; ++u) {
            int id = tid + u * 256;
            int m = id >> 4;
            int kk = (id & 15) * 4;
            float4 v = *(const float4*)(x2 + (size_t)(p0 + m) * CMID + c0 + kk);
            xs[m][kk + 0] = v.x; xs[m][kk + 1] = v.y;
            xs[m][kk + 2] = v.z; xs[m][kk + 3] = v.w;
        }
        // weights tile: 64 k x 45 (score 0..8, box 9..44)
        for (int i = tid; i < 64 * 45; i += 256) {
            int k = i / 45, n = i % 45;
            float v = (n < 9) ? wsc[(size_t)(c0 + k) * 9 + n]
                              : wbx[(size_t)(c0 + k) * 36 + (n - 9)];
            wsm[k][n] = v;
        }
        __syncthreads();
#pragma unroll 8
        for (int k = 0; k < 64; ++k) {
            float a = xs[px][k];
#pragma unroll
            for (int j = 0; j < 12; ++j) {
                int n = g + 4 * j;
                if (n < 45) acc[j] = fmaf(a, wsm[k][n], acc[j]);
            }
        }
        __syncthreads();
    }

#pragma unroll
    for (int j = 0; j < 12; ++j) {
        int n = g + 4 * j;
        if (n < 45) zb[px][n] = acc[j] + ((n < 9) ? bsc[n] : bbx[n - 9]);
    }
    __syncthreads();

    const float sqrt_r[3] = {sqrtf(0.5f), 1.0f, sqrtf(2.0f)};
    const float scales[3] = {128.f, 256.f, 512.f};

    for (int t = tid; t < 64 * NA; t += 256) {
        int p = t / NA, a = t % NA;
        int gp = p0 + p;
        int y = gp / WW, x = gp % WW;
        float zs = zb[p][a];
        float score = 1.0f / (1.0f + expf(-zs));
        float dy = zb[p][9 + 4 * a + 0];
        float dx = zb[p][9 + 4 * a + 1];
        float dh = zb[p][9 + 4 * a + 2];
        float dw = zb[p][9 + 4 * a + 3];
        int si = a / 3, ri = a % 3;
        float ah = scales[si] * sqrt_r[ri];
        float aw = scales[si] / sqrt_r[ri];
        float acy = (y + 0.5f) * 16.0f;
        float acx = (x + 0.5f) * 16.0f;
        float cy = acy + dy * ah;
        float cx = acx + dx * aw;
        float h = ah * expf(dh);
        float w = aw * expf(dw);
        float y1 = fminf(fmaxf(cy - 0.5f * h, 0.f), IMG_MAX);
        float x1 = fminf(fmaxf(cx - 0.5f * w, 0.f), IMG_MAX);
        float y2 = fminf(fmaxf(cy + 0.5f * h, 0.f), IMG_MAX);
        float x2c = fminf(fmaxf(cx + 0.5f * w, 0.f), IMG_MAX);
        int gi = gp * NA + a;
        *(float4*)(g_boxes + (size_t)gi * 4) = make_float4(y1, x1, y2, x2c);
        g_scores[gi] = score;
    }
}

// ---------------- radix sort (stable LSD, 4x8 bits, descending score) ---------
__global__ __launch_bounds__(1024)
void sort_init_kernel()
{
    int i = blockIdx.x * 1024 + threadIdx.x;
    unsigned fb = __float_as_uint(g_scores[i]);   // scores > 0 -> monotone bits
    g_key[0][i] = ~fb;                            // ascending sort => desc score
    g_val[0][i] = (unsigned)i;
}

__global__ __launch_bounds__(1024)
void sort_count_kernel(int src, int shift)
{
    __shared__ unsigned hist[256];
    int tid = threadIdx.x;
    if (tid < 256) hist[tid] = 0;
    __syncthreads();
    unsigned k = g_key[src][blockIdx.x * 1024 + tid];
    atomicAdd(&hist[(k >> shift) & 255u], 1u);
    __syncthreads();
    if (tid < 256) g_counts[tid * SBLK + blockIdx.x] = hist[tid];
}

__global__ __launch_bounds__(1024)
void sort_scan_kernel()
{
    __shared__ unsigned sums[1024];
    int tid = threadIdx.x;
    const int CH = (256 * SBLK) / 1024;   // 36
    unsigned local = 0;
    int base = tid * CH;
    for (int j = 0; j < CH; ++j) local += g_counts[base + j];
    sums[tid] = local;
    __syncthreads();
    for (int off = 1; off < 1024; off <<= 1) {
        unsigned v = 0;
        if (tid >= off) v = sums[tid - off];
        __syncthreads();
        if (tid >= off) sums[tid] += v;
        __syncthreads();
    }
    unsigned run = (tid == 0) ? 0u : sums[tid - 1];
    for (int j = 0; j < CH; ++j) {
        unsigned c = g_counts[base + j];
        g_offs[base + j] = run;
        run += c;
    }
}

__global__ __launch_bounds__(1024)
void sort_scatter_kernel(int src, int shift)
{
    __shared__ unsigned wc[32][256];
    int tid = threadIdx.x;
    int wrp = tid >> 5, ln = tid & 31;
    for (int i = tid; i < 32 * 256; i += 1024) ((unsigned*)wc)[i] = 0;
    __syncthreads();
    unsigned key = g_key[src][blockIdx.x * 1024 + tid];
    unsigned val = g_val[src][blockIdx.x * 1024 + tid];
    unsigned d = (key >> shift) & 255u;
    unsigned mask = __match_any_sync(0xffffffffu, d);
    int r = __popc(mask & ((1u << ln) - 1u));
    int leader = __ffs(mask) - 1;
    if (ln == leader) wc[wrp][d] = (unsigned)__popc(mask);
    __syncthreads();
    if (tid < 256) {
        unsigned run = 0;
        for (int w2 = 0; w2 < 32; ++w2) {
            unsigned c = wc[w2][tid];
            wc[w2][tid] = run;
            run += c;
        }
    }
    __syncthreads();
    unsigned pos = g_offs[d * SBLK + blockIdx.x] + wc[wrp][d] + (unsigned)r;
    int dst = src ^ 1;
    g_key[dst][pos] = key;
    g_val[dst][pos] = val;
}

// ---------------- NMS + output -------------------------------------------------
__device__ __forceinline__ float iou_f(float4 a, float areaA, float4 b, float areaB)
{
    float iy = fmaxf(0.f, fminf(a.z, b.z) - fmaxf(a.x, b.x));
    float ix = fmaxf(0.f, fminf(a.w, b.w) - fmaxf(a.y, b.y));
    float inter = iy * ix;
    return inter / (areaA + areaB - inter + 1e-9f);
}

__global__ __launch_bounds__(1024)
void nms_kernel(float* __restrict__ out, int out_size)
{
    __shared__ float4 selB[MAXOUT];
    __shared__ float  selA[MAXOUT];
    __shared__ float  selS[MAXOUT];
    __shared__ float4 candB[1024];
    __shared__ float  candS[1024];
    __shared__ unsigned char flag[1024];
    __shared__ int sh_count, sh_stop;

    int tid = threadIdx.x;
    if (tid == 0) { sh_count = 0; sh_stop = 0; }
    __syncthreads();

    for (int pos = 0; pos < NIT; pos += 1024) {
        int i = pos + tid;
        int idx = (int)g_val[0][i];
        float s = g_scores[idx];
        float4 b = *(const float4*)(g_boxes + (size_t)idx * 4);
        candB[tid] = b;
        candS[tid] = s;
        bool ok = (s >= 0.5f);
        if (ok) {
            float area = (b.z - b.x) * (b.w - b.y);
            int cnt = sh_count;
            for (int j = 0; j < cnt; ++j) {
                if (iou_f(b, area, selB[j], selA[j]) > 0.7f) { ok = false; break; }
            }
        }
        flag[tid] = ok ? 1 : 0;
        __syncthreads();

        if (tid < 32) {
            int cnt0 = sh_count;
            int cnt2 = cnt0;
            for (int j = 0; j < 1024 && cnt2 < MAXOUT; ++j) {
                if (candS[j] < 0.5f) { if (tid == 0) sh_stop = 1; break; }
                if (!flag[j]) continue;
                float4 cb = candB[j];
                float area = (cb.z - cb.x) * (cb.w - cb.y);
                bool sup = false;
                for (int q = cnt0 + tid; q < cnt2; q += 32) {
                    if (iou_f(cb, area, selB[q], selA[q]) > 0.7f) { sup = true; break; }
                }
                unsigned bal = __ballot_sync(0xffffffffu, sup);
                if (bal == 0u) {
                    if (tid == 0) {
                        selB[cnt2] = cb;
                        selA[cnt2] = area;
                        selS[cnt2] = candS[j];
                    }
                    cnt2++;
                    __syncwarp();
                }
            }
            if (tid == 0) {
                sh_count = cnt2;
                if (cnt2 >= MAXOUT) sh_stop = 1;
            }
        }
        __syncthreads();
        int stop = sh_stop;
        __syncthreads();
        if (stop) break;
    }

    int cnt = sh_count;
    // output layout: boxes[300][4], scores[300], valid[300] as float
    for (int r = tid; r < MAXOUT; r += 1024) {
        bool v = (r < cnt);
        float4 b = v ? selB[r] : make_float4(0.f, 0.f, 0.f, 0.f);
        if (4 * r + 3 < out_size) {
            out[4 * r + 0] = b.x; out[4 * r + 1] = b.y;
            out[4 * r + 2] = b.z; out[4 * r + 3] = b.w;
        }
        if (4 * MAXOUT + r < out_size)     out[4 * MAXOUT + r] = v ? selS[r] : 0.f;
        if (5 * MAXOUT + r < out_size)     out[5 * MAXOUT + r] = v ? 1.0f : 0.f;
    }
}

// ---------------- launcher -----------------------------------------------------
extern "C" void kernel_launch(void* const* d_in, const int* in_sizes, int n_in,
                              void* d_out, int out_size)
{
    const float* features = (const float*)d_in[0];
    const float* w1  = (const float*)d_in[1];
    const float* b1  = (const float*)d_in[2];
    const float* w2  = (const float*)d_in[3];
    const float* b2  = (const float*)d_in[4];
    const float* wsc = (const float*)d_in[5];
    const float* bsc = (const float*)d_in[6];
    const float* wbx = (const float*)d_in[7];
    const float* bbx = (const float*)d_in[8];
    (void)in_sizes; (void)n_in;

    float* x1 = nullptr; float* x2 = nullptr;
    cudaGetSymbolAddress((void**)&x1, g_x1);
    cudaGetSymbolAddress((void**)&x2, g_x2);

    // conv1: relu(in) -> conv3x3 -> +b1 -> relu
    {
        dim3 grid(CMID / 128, HH);
        conv3x3_kernel<CFEAT, true, true><<<grid, 256>>>(features, w1, b1, x1, CMID);
    }
    // conv2: conv3x3 -> +b2 (no relu)
    {
        dim3 grid(CMID / 128, HH);
        conv3x3_kernel<CMID, false, false><<<grid, 256>>>(x1, w2, b2, x2, CMID);
    }
    // heads + decode
    head_kernel<<<NPIX / 64, 256>>>(x2, wsc, bsc, wbx, bbx);

    // sort (stable LSD radix, 4 passes)
    sort_init_kernel<<<SBLK, 1024>>>();
    int src = 0;
    for (int p = 0; p < 4; ++p) {
        int shift = p * 8;
        sort_count_kernel<<<SBLK, 1024>>>(src, shift);
        sort_scan_kernel<<<1, 1024>>>();
        sort_scatter_kernel<<<SBLK, 1024>>>(src, shift);
        src ^= 1;
    }
    // after 4 passes result is back in buffer 0

    // NMS + write output
    nms_kernel<<<1, 1024>>>((float*)d_out, out_size);
}

// round 3
// speedup vs baseline: 1.0174x; 1.0174x over previous
#include <cuda_runtime.h>
#include <math.h>
#include <stdint.h>

#define HH 128
#define WW 128
#define CFEAT 1024
#define CMID 512
#define NA 9
#define NPIX (HH*WW)
#define NIT (NPIX*NA)          // 147456
#define MAXOUT 300
#define SBLK (NIT/1024)        // 144
#define IMG_MAX 2048.0f

// ---------------- scratch (device globals; no allocation allowed) -------------
__device__ float g_x1[NPIX*CMID];        // conv1 output (relu'd)
__device__ float g_x2[NPIX*CMID];        // conv2 output (no relu)
__device__ float g_boxes[NIT*4];         // decoded clipped boxes y1,x1,y2,x2
__device__ float g_scores[NIT];          // sigmoid scores
__device__ unsigned g_key[2][NIT];
__device__ unsigned g_val[2][NIT];
__device__ unsigned g_counts[256*SBLK];
__device__ unsigned g_offs[256*SBLK];

// ---------------- packed f32x2 helpers ----------------------------------------
typedef unsigned long long u64t;

__device__ __forceinline__ u64t pack2(float lo, float hi) {
    u64t r; asm("mov.b64 %0, {%1, %2};" : "=l"(r) : "f"(lo), "f"(hi)); return r;
}
__device__ __forceinline__ void unpack2(u64t v, float& lo, float& hi) {
    asm("mov.b64 {%0, %1}, %2;" : "=f"(lo), "=f"(hi) : "l"(v));
}
__device__ __forceinline__ u64t fma2(u64t a, u64t b, u64t c) {
    u64t d; asm("fma.rn.f32x2 %0, %1, %2, %3;" : "=l"(d) : "l"(a), "l"(b), "l"(c)); return d;
}

// ---------------- 3x3 conv as tiled implicit GEMM (packed f32x2) --------------
// block: 128 pixels (one image row) x 128 out-channels. 256 threads, 8x8 micro.
template<int CIN, bool RELU_IN, bool RELU_OUT>
__global__ __launch_bounds__(256, 2)
void conv3x3_kernel(const float* __restrict__ in,   // [H][W][CIN]
                    const float* __restrict__ w,    // [3][3][CIN][COUT]
                    const float* __restrict__ bias, // [COUT]
                    float* __restrict__ out,        // [H][W][COUT]
                    int COUT)
{
    const int n0  = blockIdx.x * 128;
    const int y   = blockIdx.y;
    const int tid = threadIdx.x;
    const int tx  = tid & 15;       // n dir
    const int ty  = tid >> 4;       // m dir

    __shared__ float As[16][132];
    __shared__ float Bs[16][128];

    // packed accumulators: acc2[i][j2] holds (acc[i][2j2], acc[i][2j2+1])
    u64t acc2[8][4];
#pragma unroll
    for (int i = 0; i < 8; ++i)
#pragma unroll
        for (int j = 0; j < 4; ++j) acc2[i][j] = 0ull;

#pragma unroll 1
    for (int tap = 0; tap < 9; ++tap) {
        const int ky = tap / 3, kx = tap % 3;
        const int yy = y + ky - 1;
        const bool rowok = ((unsigned)yy < (unsigned)HH);
        const float* inrow = in + (size_t)yy * WW * CIN;
        const float* wtap  = w  + (size_t)tap * CIN * COUT;

#pragma unroll 1
        for (int c0 = 0; c0 < CIN; c0 += 16) {
            // load A tile (transposed into [k][m])
#pragma unroll
            for (int u = 0; u < 2; ++u) {
                int id = tid + u * 256;
                int m  = id >> 2;
                int k4 = (id & 3) * 4;
                int xx = m + kx - 1;
                float4 v = make_float4(0.f, 0.f, 0.f, 0.f);
                if (rowok && (unsigned)xx < (unsigned)WW) {
                    v = *(const float4*)(inrow + (size_t)xx * CIN + c0 + k4);
                    if (RELU_IN) {
                        v.x = fmaxf(v.x, 0.f); v.y = fmaxf(v.y, 0.f);
                        v.z = fmaxf(v.z, 0.f); v.w = fmaxf(v.w, 0.f);
                    }
                }
                As[k4 + 0][m] = v.x; As[k4 + 1][m] = v.y;
                As[k4 + 2][m] = v.z; As[k4 + 3][m] = v.w;
            }
            // load B tile
#pragma unroll
            for (int u = 0; u < 2; ++u) {
                int id = tid + u * 256;
                int kb = id >> 5;
                int nb = (id & 31) * 4;
                float4 v = *(const float4*)(wtap + (size_t)(c0 + kb) * COUT + n0 + nb);
                *(float4*)&Bs[kb][nb] = v;
            }
            __syncthreads();
#pragma unroll
            for (int k = 0; k < 16; ++k) {
                // a: 8 values, duplicated into packed lanes
                float4 a03 = *(const float4*)&As[k][ty * 8 + 0];
                float4 a47 = *(const float4*)&As[k][ty * 8 + 4];
                u64t a2[8];
                a2[0] = pack2(a03.x, a03.x); a2[1] = pack2(a03.y, a03.y);
                a2[2] = pack2(a03.z, a03.z); a2[3] = pack2(a03.w, a03.w);
                a2[4] = pack2(a47.x, a47.x); a2[5] = pack2(a47.y, a47.y);
                a2[6] = pack2(a47.z, a47.z); a2[7] = pack2(a47.w, a47.w);
                // b: 8 values as 4 packed pairs (memory order lo,hi)
                const u64t* brow = (const u64t*)&Bs[k][tx * 8];
                u64t b2[4];
                b2[0] = brow[0]; b2[1] = brow[1]; b2[2] = brow[2]; b2[3] = brow[3];
#pragma unroll
                for (int i = 0; i < 8; ++i)
#pragma unroll
                    for (int j = 0; j < 4; ++j)
                        acc2[i][j] = fma2(a2[i], b2[j], acc2[i][j]);
            }
            __syncthreads();
        }
    }

    float bv[8];
#pragma unroll
    for (int j = 0; j < 8; ++j) bv[j] = bias[n0 + tx * 8 + j];

#pragma unroll
    for (int i = 0; i < 8; ++i) {
        int m = ty * 8 + i;
        float* orow = out + ((size_t)(y * WW + m)) * COUT + n0 + tx * 8;
        float v[8];
#pragma unroll
        for (int j = 0; j < 4; ++j)
            unpack2(acc2[i][j], v[2 * j], v[2 * j + 1]);
#pragma unroll
        for (int j = 0; j < 8; ++j) {
            v[j] = v[j] + bv[j];
            if (RELU_OUT) v[j] = fmaxf(v[j], 0.f);
        }
        *(float4*)(orow + 0) = make_float4(v[0], v[1], v[2], v[3]);
        *(float4*)(orow + 4) = make_float4(v[4], v[5], v[6], v[7]);
    }
}

// ---------------- head: 1x1 convs + sigmoid + decode --------------------------
__global__ __launch_bounds__(256)
void head_kernel(const float* __restrict__ x2,
                 const float* __restrict__ wsc, const float* __restrict__ bsc,
                 const float* __restrict__ wbx, const float* __restrict__ bbx)
{
    const int p0  = blockIdx.x * 64;     // pixel base
    const int tid = threadIdx.x;
    const int px  = tid & 63;
    const int g   = tid >> 6;            // 0..3

    __shared__ float xs[64][65];
    __shared__ float wsm[64][46];
    __shared__ float zb[64][48];

    float acc[12];
#pragma unroll
    for (int j = 0; j < 12; ++j) acc[j] = 0.f;

#pragma unroll 1
    for (int c0 = 0; c0 < CMID; c0 += 64) {
        // x2 tile: 64 px x 64 k
#pragma unroll
        for (int u = 0; u < 4; ++u) {
            int id = tid + u * 256;
            int m = id >> 4;
            int kk = (id & 15) * 4;
            float4 v = *(const float4*)(x2 + (size_t)(p0 + m) * CMID + c0 + kk);
            xs[m][kk + 0] = v.x; xs[m][kk + 1] = v.y;
            xs[m][kk + 2] = v.z; xs[m][kk + 3] = v.w;
        }
        // weights tile: 64 k x 45 (score 0..8, box 9..44)
        for (int i = tid; i < 64 * 45; i += 256) {
            int k = i / 45, n = i % 45;
            float v = (n < 9) ? wsc[(size_t)(c0 + k) * 9 + n]
                              : wbx[(size_t)(c0 + k) * 36 + (n - 9)];
            wsm[k][n] = v;
        }
        __syncthreads();
#pragma unroll 8
        for (int k = 0; k < 64; ++k) {
            float a = xs[px][k];
#pragma unroll
            for (int j = 0; j < 12; ++j) {
                int n = g + 4 * j;
                if (n < 45) acc[j] = fmaf(a, wsm[k][n], acc[j]);
            }
        }
        __syncthreads();
    }

#pragma unroll
    for (int j = 0; j < 12; ++j) {
        int n = g + 4 * j;
        if (n < 45) zb[px][n] = acc[j] + ((n < 9) ? bsc[n] : bbx[n - 9]);
    }
    __syncthreads();

    const float sqrt_r[3] = {sqrtf(0.5f), 1.0f, sqrtf(2.0f)};
    const float scales[3] = {128.f, 256.f, 512.f};

    for (int t = tid; t < 64 * NA; t += 256) {
        int p = t / NA, a = t % NA;
        int gp = p0 + p;
        int y = gp / WW, x = gp % WW;
        float zs = zb[p][a];
        float score = 1.0f / (1.0f + expf(-zs));
        float dy = zb[p][9 + 4 * a + 0];
        float dx = zb[p][9 + 4 * a + 1];
        float dh = zb[p][9 + 4 * a + 2];
        float dw = zb[p][9 + 4 * a + 3];
        int si = a / 3, ri = a % 3;
        float ah = scales[si] * sqrt_r[ri];
        float aw = scales[si] / sqrt_r[ri];
        float acy = (y + 0.5f) * 16.0f;
        float acx = (x + 0.5f) * 16.0f;
        float cy = acy + dy * ah;
        float cx = acx + dx * aw;
        float h = ah * expf(dh);
        float w = aw * expf(dw);
        float y1 = fminf(fmaxf(cy - 0.5f * h, 0.f), IMG_MAX);
        float x1 = fminf(fmaxf(cx - 0.5f * w, 0.f), IMG_MAX);
        float y2 = fminf(fmaxf(cy + 0.5f * h, 0.f), IMG_MAX);
        float x2c = fminf(fmaxf(cx + 0.5f * w, 0.f), IMG_MAX);
        int gi = gp * NA + a;
        *(float4*)(g_boxes + (size_t)gi * 4) = make_float4(y1, x1, y2, x2c);
        g_scores[gi] = score;
    }
}

// ---------------- radix sort (stable LSD, 4x8 bits, descending score) ---------
__global__ __launch_bounds__(1024)
void sort_init_kernel()
{
    int i = blockIdx.x * 1024 + threadIdx.x;
    unsigned fb = __float_as_uint(g_scores[i]);   // scores > 0 -> monotone bits
    g_key[0][i] = ~fb;                            // ascending sort => desc score
    g_val[0][i] = (unsigned)i;
}

__global__ __launch_bounds__(1024)
void sort_count_kernel(int src, int shift)
{
    __shared__ unsigned hist[256];
    int tid = threadIdx.x;
    if (tid < 256) hist[tid] = 0;
    __syncthreads();
    unsigned k = g_key[src][blockIdx.x * 1024 + tid];
    atomicAdd(&hist[(k >> shift) & 255u], 1u);
    __syncthreads();
    if (tid < 256) g_counts[tid * SBLK + blockIdx.x] = hist[tid];
}

__global__ __launch_bounds__(1024)
void sort_scan_kernel()
{
    __shared__ unsigned sums[1024];
    int tid = threadIdx.x;
    const int CH = (256 * SBLK) / 1024;   // 36
    unsigned local = 0;
    int base = tid * CH;
    for (int j = 0; j < CH; ++j) local += g_counts[base + j];
    sums[tid] = local;
    __syncthreads();
    for (int off = 1; off < 1024; off <<= 1) {
        unsigned v = 0;
        if (tid >= off) v = sums[tid - off];
        __syncthreads();
        if (tid >= off) sums[tid] += v;
        __syncthreads();
    }
    unsigned run = (tid == 0) ? 0u : sums[tid - 1];
    for (int j = 0; j < CH; ++j) {
        unsigned c = g_counts[base + j];
        g_offs[base + j] = run;
        run += c;
    }
}

__global__ __launch_bounds__(1024)
void sort_scatter_kernel(int src, int shift)
{
    __shared__ unsigned wc[32][256];
    int tid = threadIdx.x;
    int wrp = tid >> 5, ln = tid & 31;
    for (int i = tid; i < 32 * 256; i += 1024) ((unsigned*)wc)[i] = 0;
    __syncthreads();
    unsigned key = g_key[src][blockIdx.x * 1024 + tid];
    unsigned val = g_val[src][blockIdx.x * 1024 + tid];
    unsigned d = (key >> shift) & 255u;
    unsigned mask = __match_any_sync(0xffffffffu, d);
    int r = __popc(mask & ((1u << ln) - 1u));
    int leader = __ffs(mask) - 1;
    if (ln == leader) wc[wrp][d] = (unsigned)__popc(mask);
    __syncthreads();
    if (tid < 256) {
        unsigned run = 0;
        for (int w2 = 0; w2 < 32; ++w2) {
            unsigned c = wc[w2][tid];
            wc[w2][tid] = run;
            run += c;
        }
    }
    __syncthreads();
    unsigned pos = g_offs[d * SBLK + blockIdx.x] + wc[wrp][d] + (unsigned)r;
    int dst = src ^ 1;
    g_key[dst][pos] = key;
    g_val[dst][pos] = val;
}

// ---------------- NMS + output -------------------------------------------------
__device__ __forceinline__ float iou_f(float4 a, float areaA, float4 b, float areaB)
{
    float iy = fmaxf(0.f, fminf(a.z, b.z) - fmaxf(a.x, b.x));
    float ix = fmaxf(0.f, fminf(a.w, b.w) - fmaxf(a.y, b.y));
    float inter = iy * ix;
    return inter / (areaA + areaB - inter + 1e-9f);
}

__global__ __launch_bounds__(1024)
void nms_kernel(float* __restrict__ out, int out_size)
{
    __shared__ float4 selB[MAXOUT];
    __shared__ float  selA[MAXOUT];
    __shared__ float  selS[MAXOUT];
    __shared__ float4 candB[1024];
    __shared__ float  candS[1024];
    __shared__ unsigned char flag[1024];
    __shared__ int sh_count, sh_stop;

    int tid = threadIdx.x;
    if (tid == 0) { sh_count = 0; sh_stop = 0; }
    __syncthreads();

    for (int pos = 0; pos < NIT; pos += 1024) {
        int i = pos + tid;
        int idx = (int)g_val[0][i];
        float s = g_scores[idx];
        float4 b = *(const float4*)(g_boxes + (size_t)idx * 4);
        candB[tid] = b;
        candS[tid] = s;
        bool ok = (s >= 0.5f);
        if (ok) {
            float area = (b.z - b.x) * (b.w - b.y);
            int cnt = sh_count;
            for (int j = 0; j < cnt; ++j) {
                if (iou_f(b, area, selB[j], selA[j]) > 0.7f) { ok = false; break; }
            }
        }
        flag[tid] = ok ? 1 : 0;
        __syncthreads();

        if (tid < 32) {
            int cnt0 = sh_count;
            int cnt2 = cnt0;
            for (int j = 0; j < 1024 && cnt2 < MAXOUT; ++j) {
                if (candS[j] < 0.5f) { if (tid == 0) sh_stop = 1; break; }
                if (!flag[j]) continue;
                float4 cb = candB[j];
                float area = (cb.z - cb.x) * (cb.w - cb.y);
                bool sup = false;
                for (int q = cnt0 + tid; q < cnt2; q += 32) {
                    if (iou_f(cb, area, selB[q], selA[q]) > 0.7f) { sup = true; break; }
                }
                unsigned bal = __ballot_sync(0xffffffffu, sup);
                if (bal == 0u) {
                    if (tid == 0) {
                        selB[cnt2] = cb;
                        selA[cnt2] = area;
                        selS[cnt2] = candS[j];
                    }
                    cnt2++;
                    __syncwarp();
                }
            }
            if (tid == 0) {
                sh_count = cnt2;
                if (cnt2 >= MAXOUT) sh_stop = 1;
            }
        }
        __syncthreads();
        int stop = sh_stop;
        __syncthreads();
        if (stop) break;
    }

    int cnt = sh_count;
    // output layout: boxes[300][4], scores[300], valid[300] as float
    for (int r = tid; r < MAXOUT; r += 1024) {
        bool v = (r < cnt);
        float4 b = v ? selB[r] : make_float4(0.f, 0.f, 0.f, 0.f);
        if (4 * r + 3 < out_size) {
            out[4 * r + 0] = b.x; out[4 * r + 1] = b.y;
            out[4 * r + 2] = b.z; out[4 * r + 3] = b.w;
        }
        if (4 * MAXOUT + r < out_size)     out[4 * MAXOUT + r] = v ? selS[r] : 0.f;
        if (5 * MAXOUT + r < out_size)     out[5 * MAXOUT + r] = v ? 1.0f : 0.f;
    }
}

// ---------------- launcher -----------------------------------------------------
extern "C" void kernel_launch(void* const* d_in, const int* in_sizes, int n_in,
                              void* d_out, int out_size)
{
    const float* features = (const float*)d_in[0];
    const float* w1  = (const float*)d_in[1];
    const float* b1  = (const float*)d_in[2];
    const float* w2  = (const float*)d_in[3];
    const float* b2  = (const float*)d_in[4];
    const float* wsc = (const float*)d_in[5];
    const float* bsc = (const float*)d_in[6];
    const float* wbx = (const float*)d_in[7];
    const float* bbx = (const float*)d_in[8];
    (void)in_sizes; (void)n_in;

    float* x1 = nullptr; float* x2 = nullptr;
    cudaGetSymbolAddress((void**)&x1, g_x1);
    cudaGetSymbolAddress((void**)&x2, g_x2);

    // conv1: relu(in) -> conv3x3 -> +b1 -> relu
    {
        dim3 grid(CMID / 128, HH);
        conv3x3_kernel<CFEAT, true, true><<<grid, 256>>>(features, w1, b1, x1, CMID);
    }
    // conv2: conv3x3 -> +b2 (no relu)
    {
        dim3 grid(CMID / 128, HH);
        conv3x3_kernel<CMID, false, false><<<grid, 256>>>(x1, w2, b2, x2, CMID);
    }
    // heads + decode
    head_kernel<<<NPIX / 64, 256>>>(x2, wsc, bsc, wbx, bbx);

    // sort (stable LSD radix, 4 passes)
    sort_init_kernel<<<SBLK, 1024>>>();
    int src = 0;
    for (int p = 0; p < 4; ++p) {
        int shift = p * 8;
        sort_count_kernel<<<SBLK, 1024>>>(src, shift);
        sort_scan_kernel<<<1, 1024>>>();
        sort_scatter_kernel<<<SBLK, 1024>>>(src, shift);
        src ^= 1;
    }
    // after 4 passes result is back in buffer 0

    // NMS + write output
    nms_kernel<<<1, 1024>>>((float*)d_out, out_size);
}